// round 12
// baseline (speedup 1.0000x reference)
#include <cuda_runtime.h>
#include <math.h>

#define NB   512
#define CIN  156
#define COUT 50
#define TT   325
#define THREADS 256

#define CCH   12
#define NCH   13
#define NPAIR 6

// conv: 6 pairs x 41 t-groups, tile 4
#define CNTG  41
#define CTILE 4
#define CACT  246

// gemm (proven): 10 o-groups (5 o each) x 21 t-groups (4 ulls = 8 t each)
#define GNTG  21
#define GACT  210

#define XROW2F 544                 // floats per interleaved pair row (272 ulls)
#define XI2BUF (NPAIR*XROW2F)      // 3264 floats
#define PSTR   168
#define PSPBUF (CCH*PSTR)          // 2016 floats
#define WDBUF  (CCH*COUT*2)        // 1200 floats (dup ulls)

// smem float offsets (per CTA, 52,640 B -> 3 CTAs/SM)
#define OFF_EPS 0                  // 200
#define OFF_WD  200                // 2 x 1200
#define OFF_PSP 2600               // 2 x 2016
#define OFF_XI2 6632               // 2 x 3264
#define SMEM_FLOATS 13160
#define OFF_YST OFF_PSP            // y staging [168][52]=8736 fl (reuses PSP+XI2=10560)

#define SROWS (NB*COUT)            // 25600

typedef unsigned long long ull;

__device__ float g_y[(size_t)TT * SROWS];   // t-major scratch, 33.3 MB

__device__ __forceinline__ ull pack2(float lo, float hi) {
    ull r; asm("mov.b64 %0, {%1, %2};" : "=l"(r) : "f"(lo), "f"(hi)); return r;
}
__device__ __forceinline__ void unpack2(ull v, float &lo, float &hi) {
    asm("mov.b64 {%0, %1}, %2;" : "=f"(lo), "=f"(hi) : "l"(v));
}
__device__ __forceinline__ void fma2(ull &d, ull a, ull b) {
    asm("fma.rn.f32x2 %0, %1, %2, %0;" : "+l"(d) : "l"(a), "l"(b));
}
__device__ __forceinline__ unsigned smem_u32(const void* p) {
    return (unsigned)__cvta_generic_to_shared(p);
}
__device__ __forceinline__ void cpa4(unsigned dst, const float* src) {
    asm volatile("cp.async.ca.shared.global [%0], [%1], 4;" :: "r"(dst), "l"(src));
}
__device__ __forceinline__ void cpa_commit() { asm volatile("cp.async.commit_group;"); }

__global__ __launch_bounds__(THREADS, 3)
void convgemm_kernel(const float* __restrict__ x, const float* __restrict__ w)
{
    extern __shared__ float sm[];
    const int tid = threadIdx.x;
    const int b   = blockIdx.x >> 1;
    const int h   = blockIdx.x & 1;
    const int len = 163 - h;               // 163 / 162
    const int t0h = h * 163;
    const int pstart = h ? 0 : 100;
    const int cnt = 100 + len - pstart;

    // ---- init: eps taps (jnp op sequence), x pads, psp tails ----
    if (tid < 100) {
        float tk = (float)tid / 10.0f;
        float e  = tk * expf(1.0f - tk);
        ((ull*)(sm + OFF_EPS))[tid] = pack2(e, e);
    }
    for (int i = tid; i < NPAIR * 200 * 2; i += THREADS) {       // zero x pads, both bufs
        int buf = i / (NPAIR * 200), rem = i % (NPAIR * 200);
        sm[OFF_XI2 + buf * XI2BUF + (rem / 200) * XROW2F + (rem % 200)] = 0.0f;
    }
    for (int i = tid; i < 2 * CCH * (PSTR - len); i += THREADS) {  // zero psp tails
        int buf = i / (CCH * (PSTR - len)), rem = i % (CCH * (PSTR - len));
        int row = rem / (PSTR - len), off = rem % (PSTR - len);
        sm[OFF_PSP + buf * PSPBUF + row * PSTR + len + off] = 0.0f;
    }

    // ---- prologue: issue x chunk 0, load w chunk 0 into regs ----
    {
        const float* xb = x + ((size_t)b * CIN) * TT + (t0h - 100);
        for (int i = tid; i < CCH * cnt; i += THREADS) {
            int cl = i / cnt, p = pstart + i % cnt;
            cpa4(smem_u32(sm + OFF_XI2 + (cl >> 1) * XROW2F + 2 * p + (cl & 1)),
                 xb + cl * TT + p);
        }
        cpa_commit();
    }
    float wR[3];
    {
        int j = 0;
        for (int i = tid; i < CCH * COUT; i += THREADS, j++) {
            int o = i / CCH, cl = i % CCH;
            wR[j] = w[o * CIN + cl];
        }
    }

    // thread mappings
    const int cpr = tid / CNTG, ctg = tid % CNTG;
    const int ct0 = ctg * CTILE;
    const bool cact = (tid < CACT);
    const ull* e2 = (const ull*)(sm + OFF_EPS);

    const int og = tid / GNTG, gtg = tid % GNTG;
    const int gt0fl = gtg * 8;
    const bool gact = (tid < GACT);

    ull acc[5][4];
    #pragma unroll
    for (int m = 0; m < 5; m++)
        #pragma unroll
        for (int q = 0; q < 4; q++) acc[m][q] = 0ULL;

    // ---- pipelined main loop: ONE barrier per chunk ----
    // body cc: issue x[cc+1] | write Wd[cc] | conv[cc] | GEMM[cc-1]
    for (int cc = 0; cc < NCH; cc++) {
        asm volatile("cp.async.wait_group 0;");
        __syncthreads();
        // barrier[cc]: x[cc] visible; PSP/Wd[cc-1] visible; conv[cc-1] reads done.

        if (cc + 1 < NCH) {
            const float* xb = x + ((size_t)b * CIN + (cc + 1) * CCH) * TT + (t0h - 100);
            float* dstb = sm + OFF_XI2 + ((cc + 1) & 1) * XI2BUF;
            for (int i = tid; i < CCH * cnt; i += THREADS) {
                int cl = i / cnt, p = pstart + i % cnt;
                cpa4(smem_u32(dstb + (cl >> 1) * XROW2F + 2 * p + (cl & 1)),
                     xb + cl * TT + p);
            }
            cpa_commit();
        }

        // Wd[cc&1] from wR; prefetch w[cc+1] into regs
        {
            float* wdst = sm + OFF_WD + (cc & 1) * WDBUF;
            int j = 0;
            for (int i = tid; i < CCH * COUT; i += THREADS, j++) {
                int o = i / CCH, cl = i % CCH;
                wdst[(cl * COUT + o) * 2]     = wR[j];
                wdst[(cl * COUT + o) * 2 + 1] = wR[j];
            }
            if (cc + 1 < NCH) {
                j = 0;
                for (int i = tid; i < CCH * COUT; i += THREADS, j++) {
                    int o = i / CCH, cl = i % CCH;
                    wR[j] = w[o * CIN + (cc + 1) * CCH + cl];
                }
            }
        }

        // ---- conv[cc]: 100-tap FIR, ascending k, shift window (proven form) ----
        if (cact) {
            const float* rowf = sm + OFF_XI2 + (cc & 1) * XI2BUF + cpr * XROW2F;
            float* pspb = sm + OFF_PSP + (cc & 1) * PSPBUF;
            ull acc2[CTILE];
            #pragma unroll
            for (int j = 0; j < CTILE; j++) acc2[j] = 0ULL;

            ull W[8];
            {
                const ulonglong2* p = (const ulonglong2*)(rowf + 2 * (96 + ct0));
                #pragma unroll
                for (int m = 0; m < 4; m++) { ulonglong2 v = p[m]; W[2*m] = v.x; W[2*m+1] = v.y; }
            }
            #pragma unroll
            for (int kk = 0; kk < 100; kk += 4) {
                #pragma unroll
                for (int i = 0; i < 4; i++) {
                    ull ek = e2[kk + i];
                    #pragma unroll
                    for (int j = 0; j < CTILE; j++)
                        fma2(acc2[j], ek, W[j - i + 4]);
                }
                if (kk < 96) {
                    #pragma unroll
                    for (int m = 7; m >= 4; m--) W[m] = W[m - 4];
                    const ulonglong2* p = (const ulonglong2*)(rowf + 2 * (92 + ct0 - kk));
                    ulonglong2 v0 = p[0], v1 = p[1];
                    W[0] = v0.x; W[1] = v0.y; W[2] = v1.x; W[3] = v1.y;
                }
            }
            #pragma unroll
            for (int j = 0; j < CTILE; j++) {
                int t = ct0 + j;
                if (t < len) {
                    float lo, hi; unpack2(acc2[j], lo, hi);
                    pspb[(2 * cpr)     * PSTR + t] = lo;
                    pspb[(2 * cpr + 1) * PSTR + t] = hi;
                }
            }
        }

        // ---- GEMM[cc-1] (proven form, buffered operands) ----
        if (cc > 0 && gact) {
            const int g = cc - 1;
            const float* pspb = sm + OFF_PSP + (g & 1) * PSPBUF;
            const ull* wdb = (const ull*)(sm + OFF_WD + (g & 1) * WDBUF);
            #pragma unroll 2
            for (int cl = 0; cl < CCH; cl++) {
                const ulonglong2* xp = (const ulonglong2*)(pspb + cl * PSTR + gt0fl);
                ulonglong2 x01 = xp[0], x23 = xp[1];
                const ull* wd = wdb + cl * COUT + og * 5;
                ull wv[5];
                #pragma unroll
                for (int m = 0; m < 5; m++) wv[m] = wd[m];
                #pragma unroll
                for (int m = 0; m < 5; m++) {
                    fma2(acc[m][0], wv[m], x01.x);
                    fma2(acc[m][1], wv[m], x01.y);
                    fma2(acc[m][2], wv[m], x23.x);
                    fma2(acc[m][3], wv[m], x23.y);
                }
            }
        }
    }

    // ---- drain: GEMM[12] (parity (NCH-1)&1 = 0) ----
    __syncthreads();
    if (gact) {
        const float* pspb = sm + OFF_PSP + ((NCH - 1) & 1) * PSPBUF;
        const ull* wdb = (const ull*)(sm + OFF_WD + ((NCH - 1) & 1) * WDBUF);
        #pragma unroll 2
        for (int cl = 0; cl < CCH; cl++) {
            const ulonglong2* xp = (const ulonglong2*)(pspb + cl * PSTR + gt0fl);
            ulonglong2 x01 = xp[0], x23 = xp[1];
            const ull* wd = wdb + cl * COUT + og * 5;
            ull wv[5];
            #pragma unroll
            for (int m = 0; m < 5; m++) wv[m] = wd[m];
            #pragma unroll
            for (int m = 0; m < 5; m++) {
                fma2(acc[m][0], wv[m], x01.x);
                fma2(acc[m][1], wv[m], x01.y);
                fma2(acc[m][2], wv[m], x23.x);
                fma2(acc[m][3], wv[m], x23.y);
            }
        }
    }

    // ---- stage y t-major in smem (PSP/XI2 now dead), coalesced global store ----
    __syncthreads();
    if (gact) {
        #pragma unroll
        for (int m = 0; m < 5; m++) {
            int o = og * 5 + m;
            #pragma unroll
            for (int q = 0; q < 4; q++) {
                int t = 2 * (gtg * 4 + q);
                float lo, hi; unpack2(acc[m][q], lo, hi);
                sm[OFF_YST + t * 52 + o]       = lo;
                sm[OFF_YST + (t + 1) * 52 + o] = hi;
            }
        }
    }
    __syncthreads();
    {
        float* yb = g_y + (size_t)t0h * SROWS + b * COUT;
        for (int i = tid; i < len * COUT; i += THREADS) {
            int t = i / COUT, o = i % COUT;
            yb[(size_t)t * SROWS + o] = sm[OFF_YST + t * 52 + o];
        }
    }
}

// ---- scan: coalesced t-major reads, bit-exact refractory recursion (proven verbatim) ----
#define SC_SMEM ((2*32*256 + 256*33) * 4)    // 99,328 B

__global__ __launch_bounds__(256, 2)
void scan_kernel(float* __restrict__ out)
{
    extern __shared__ float ss[];
    float* sbuf = ss + 2 * 32 * 256;
    const int tid = threadIdx.x;
    const int r0 = blockIdx.x * 256;

    {   // prefetch tile 0
        const float* src = g_y + r0;
        for (int j = tid; j < 32 * 256; j += 256) {
            int t = j >> 8, col = j & 255;
            cpa4(smem_u32(ss + t * 256 + col), src + (size_t)t * SROWS + col);
        }
        cpa_commit();
    }

    float nu1[31];
    #pragma unroll
    for (int d = 1; d <= 31; d++) {
        float td = (float)d;
        nu1[d - 1] = (-20.0f * td) * expf(1.0f - td);
    }
    float rf[32];
    #pragma unroll
    for (int i = 0; i < 32; i++) rf[i] = 0.0f;

    for (int tile = 0; tile < 11; tile++) {
        const int tl = (tile == 10) ? 5 : 32;
        if (tile < 10) {
            const int nt = (tile == 9) ? 5 : 32;
            const float* src = g_y + (size_t)(tile + 1) * 32 * SROWS + r0;
            float* dst = ss + ((tile + 1) & 1) * (32 * 256);
            for (int j = tid; j < nt * 256; j += 256) {
                int t = j >> 8, col = j & 255;
                cpa4(smem_u32(dst + t * 256 + col), src + (size_t)t * SROWS + col);
            }
            cpa_commit();
            asm volatile("cp.async.wait_group 1;");
        } else {
            asm volatile("cp.async.wait_group 0;");
        }
        __syncthreads();

        const float* yb = ss + (tile & 1) * (32 * 256);
        #pragma unroll 8
        for (int t = 0; t < tl; t++) {
            float v = yb[t * 256 + tid] + rf[0];
            float s = (v >= 10.0f) ? 1.0f : 0.0f;
            sbuf[tid * 33 + t] = s;
            #pragma unroll
            for (int i = 0; i < 31; i++) rf[i] = fmaf(s, nu1[i], rf[i + 1]);
            rf[31] = 0.0f;
        }
        __syncthreads();

        const int tbase = tile * 32;
        const int lane = tid & 31;
        for (int base = 0; base < 256; base += 8) {
            int row = base + (tid >> 5);
            if (lane < tl)
                out[(size_t)(r0 + row) * TT + tbase + lane] = sbuf[row * 33 + lane];
        }
        // loop-top __syncthreads orders flush reads before next tile's writes
    }
}

extern "C" void kernel_launch(void* const* d_in, const int* in_sizes, int n_in,
                              void* d_out, int out_size)
{
    const float* x = (const float*)d_in[0];
    const float* w = (const float*)d_in[1];
    if (n_in >= 2 && in_sizes[0] == COUT * CIN) {
        x = (const float*)d_in[1];
        w = (const float*)d_in[0];
    }
    cudaFuncSetAttribute(convgemm_kernel, cudaFuncAttributeMaxDynamicSharedMemorySize,
                         SMEM_FLOATS * (int)sizeof(float));
    cudaFuncSetAttribute(scan_kernel, cudaFuncAttributeMaxDynamicSharedMemorySize,
                         SC_SMEM);
    convgemm_kernel<<<NB * 2, THREADS, SMEM_FLOATS * sizeof(float)>>>(x, w);
    scan_kernel<<<SROWS / 256, 256, SC_SMEM>>>((float*)d_out);
}

// round 14
// speedup vs baseline: 1.0057x; 1.0057x over previous
#include <cuda_runtime.h>
#include <math.h>

#define NB   512
#define CIN  156
#define COUT 50
#define TT   325
#define THREADS 288

#define CCH   26
#define NCH   6
#define NPAIR 13

// conv: 13 pairs x 21 t-groups, tile 8 (proven shift-4 family)
#define CNTG  21
#define CTILE 8
#define CACT  273

// gemm (proven): 10 o-groups (5 o each) x 21 t-groups (4 ulls = 8 t each)
#define GNTG  21
#define GACT  210

#define XROW2F 544                 // floats per interleaved pair row (272 ulls)
#define XI2BUF (NPAIR*XROW2F)      // 7072 floats
#define PSTR   168
#define PSPBUF (CCH*PSTR)          // 4368 floats
#define WDBUF  (CCH*COUT*2)        // 2600 floats (dup ulls)

// smem float offsets (per CTA, 113,120 B -> 2 CTAs/SM)
#define OFF_EPS 0                  // 200
#define OFF_WD  200                // 2 x 2600
#define OFF_PSP 5400               // 2 x 4368
#define OFF_XI2 14136              // 2 x 7072
#define SMEM_FLOATS 28280
#define OFF_YST OFF_XI2            // y staging [164][52] t-major (reuses XI2)

#define SROWS (NB*COUT)            // 25600

typedef unsigned long long ull;

__device__ float g_y[(size_t)TT * SROWS];   // t-major scratch, 33.3 MB

__device__ __forceinline__ ull pack2(float lo, float hi) {
    ull r; asm("mov.b64 %0, {%1, %2};" : "=l"(r) : "f"(lo), "f"(hi)); return r;
}
__device__ __forceinline__ void unpack2(ull v, float &lo, float &hi) {
    asm("mov.b64 {%0, %1}, %2;" : "=f"(lo), "=f"(hi) : "l"(v));
}
__device__ __forceinline__ void fma2(ull &d, ull a, ull b) {
    asm("fma.rn.f32x2 %0, %1, %2, %0;" : "+l"(d) : "l"(a), "l"(b));
}
__device__ __forceinline__ unsigned smem_u32(const void* p) {
    return (unsigned)__cvta_generic_to_shared(p);
}
__device__ __forceinline__ void cpa4(unsigned dst, const float* src) {
    asm volatile("cp.async.ca.shared.global [%0], [%1], 4;" :: "r"(dst), "l"(src));
}
__device__ __forceinline__ void cpa_commit() { asm volatile("cp.async.commit_group;"); }

__global__ __launch_bounds__(THREADS, 2)
void convgemm_kernel(const float* __restrict__ x, const float* __restrict__ w)
{
    extern __shared__ float sm[];
    const int tid = threadIdx.x;
    const int b   = blockIdx.x >> 1;
    const int h   = blockIdx.x & 1;
    const int len = 163 - h;               // 163 / 162
    const int t0h = h * 163;
    const int pstart = h ? 0 : 100;
    const int cnt = 100 + len - pstart;

    // ---- init: eps taps (jnp op sequence), x pads, psp tails ----
    if (tid < 100) {
        float tk = (float)tid / 10.0f;
        float e  = tk * expf(1.0f - tk);
        ((ull*)(sm + OFF_EPS))[tid] = pack2(e, e);
    }
    for (int i = tid; i < NPAIR * 200 * 2; i += THREADS) {       // zero x pads, both bufs
        int buf = i / (NPAIR * 200), rem = i % (NPAIR * 200);
        sm[OFF_XI2 + buf * XI2BUF + (rem / 200) * XROW2F + (rem % 200)] = 0.0f;
    }
    for (int i = tid; i < 2 * CCH * (PSTR - len); i += THREADS) {  // zero psp tails
        int buf = i / (CCH * (PSTR - len)), rem = i % (CCH * (PSTR - len));
        int row = rem / (PSTR - len), off = rem % (PSTR - len);
        sm[OFF_PSP + buf * PSPBUF + row * PSTR + len + off] = 0.0f;
    }

    // ---- prologue: issue x chunk 0, load w chunk 0 into regs ----
    {
        const float* xb = x + ((size_t)b * CIN) * TT + (t0h - 100);
        for (int i = tid; i < CCH * cnt; i += THREADS) {
            int cl = i / cnt, p = pstart + i % cnt;
            cpa4(smem_u32(sm + OFF_XI2 + (cl >> 1) * XROW2F + 2 * p + (cl & 1)),
                 xb + cl * TT + p);
        }
        cpa_commit();
    }
    float wR[5];
    {
        int j = 0;
        for (int i = tid; i < CCH * COUT; i += THREADS, j++) {
            int o = i / CCH, cl = i % CCH;
            wR[j] = w[o * CIN + cl];
        }
    }

    // thread mappings
    const int cpr = tid / CNTG, ctg = tid % CNTG;
    const int ct0 = ctg * CTILE;
    const bool cact = (tid < CACT);
    const ull* e2 = (const ull*)(sm + OFF_EPS);

    const int og = tid / GNTG, gtg = tid % GNTG;
    const int gt0fl = gtg * 8;
    const bool gact = (tid < GACT);

    ull acc[5][4];
    #pragma unroll
    for (int m = 0; m < 5; m++)
        #pragma unroll
        for (int q = 0; q < 4; q++) acc[m][q] = 0ULL;

    // ---- pipelined main loop: ONE barrier per chunk ----
    // body cc: issue x[cc+1] | write Wd[cc] | conv[cc] | GEMM[cc-1]
    for (int cc = 0; cc < NCH; cc++) {
        asm volatile("cp.async.wait_group 0;");
        __syncthreads();
        // barrier[cc]: x[cc] visible; PSP/Wd[cc-1] visible; conv[cc-1] reads done.

        if (cc + 1 < NCH) {
            const float* xb = x + ((size_t)b * CIN + (cc + 1) * CCH) * TT + (t0h - 100);
            float* dstb = sm + OFF_XI2 + ((cc + 1) & 1) * XI2BUF;
            for (int i = tid; i < CCH * cnt; i += THREADS) {
                int cl = i / cnt, p = pstart + i % cnt;
                cpa4(smem_u32(dstb + (cl >> 1) * XROW2F + 2 * p + (cl & 1)),
                     xb + cl * TT + p);
            }
            cpa_commit();
        }

        // Wd[cc&1] from wR; prefetch w[cc+1] into regs
        {
            float* wdst = sm + OFF_WD + (cc & 1) * WDBUF;
            int j = 0;
            for (int i = tid; i < CCH * COUT; i += THREADS, j++) {
                int o = i / CCH, cl = i % CCH;
                wdst[(cl * COUT + o) * 2]     = wR[j];
                wdst[(cl * COUT + o) * 2 + 1] = wR[j];
            }
            if (cc + 1 < NCH) {
                j = 0;
                for (int i = tid; i < CCH * COUT; i += THREADS, j++) {
                    int o = i / CCH, cl = i % CCH;
                    wR[j] = w[o * CIN + (cc + 1) * CCH + cl];
                }
            }
        }

        // ---- conv[cc]: 100-tap FIR, ascending k, shift-4 window W[12] (proven family) ----
        if (cact) {
            const float* rowf = sm + OFF_XI2 + (cc & 1) * XI2BUF + cpr * XROW2F;
            float* pspb = sm + OFF_PSP + (cc & 1) * PSPBUF;
            ull acc2[CTILE];
            #pragma unroll
            for (int j = 0; j < CTILE; j++) acc2[j] = 0ULL;

            ull W[12];
            {
                const ulonglong2* p = (const ulonglong2*)(rowf + 2 * (96 + ct0));
                #pragma unroll
                for (int m = 0; m < 6; m++) { ulonglong2 v = p[m]; W[2*m] = v.x; W[2*m+1] = v.y; }
            }
            #pragma unroll
            for (int kk = 0; kk < 100; kk += 4) {
                #pragma unroll
                for (int i = 0; i < 4; i++) {
                    ull ek = e2[kk + i];
                    #pragma unroll
                    for (int j = 0; j < CTILE; j++)
                        fma2(acc2[j], ek, W[j - i + 4]);
                }
                if (kk < 96) {
                    #pragma unroll
                    for (int m = 11; m >= 4; m--) W[m] = W[m - 4];
                    const ulonglong2* p = (const ulonglong2*)(rowf + 2 * (92 + ct0 - kk));
                    ulonglong2 v0 = p[0], v1 = p[1];
                    W[0] = v0.x; W[1] = v0.y; W[2] = v1.x; W[3] = v1.y;
                }
            }
            #pragma unroll
            for (int j = 0; j < CTILE; j++) {
                int t = ct0 + j;
                if (t < len) {
                    float lo, hi; unpack2(acc2[j], lo, hi);
                    pspb[(2 * cpr)     * PSTR + t] = lo;
                    pspb[(2 * cpr + 1) * PSTR + t] = hi;
                }
            }
        }

        // ---- GEMM[cc-1] (proven form, buffered operands) ----
        if (cc > 0 && gact) {
            const int g = cc - 1;
            const float* pspb = sm + OFF_PSP + (g & 1) * PSPBUF;
            const ull* wdb = (const ull*)(sm + OFF_WD + (g & 1) * WDBUF);
            #pragma unroll 2
            for (int cl = 0; cl < CCH; cl++) {
                const ulonglong2* xp = (const ulonglong2*)(pspb + cl * PSTR + gt0fl);
                ulonglong2 x01 = xp[0], x23 = xp[1];
                const ull* wd = wdb + cl * COUT + og * 5;
                ull wv[5];
                #pragma unroll
                for (int m = 0; m < 5; m++) wv[m] = wd[m];
                #pragma unroll
                for (int m = 0; m < 5; m++) {
                    fma2(acc[m][0], wv[m], x01.x);
                    fma2(acc[m][1], wv[m], x01.y);
                    fma2(acc[m][2], wv[m], x23.x);
                    fma2(acc[m][3], wv[m], x23.y);
                }
            }
        }
    }

    // ---- drain: GEMM[5] ----
    __syncthreads();
    if (gact) {
        const float* pspb = sm + OFF_PSP + ((NCH - 1) & 1) * PSPBUF;
        const ull* wdb = (const ull*)(sm + OFF_WD + ((NCH - 1) & 1) * WDBUF);
        #pragma unroll 2
        for (int cl = 0; cl < CCH; cl++) {
            const ulonglong2* xp = (const ulonglong2*)(pspb + cl * PSTR + gt0fl);
            ulonglong2 x01 = xp[0], x23 = xp[1];
            const ull* wd = wdb + cl * COUT + og * 5;
            ull wv[5];
            #pragma unroll
            for (int m = 0; m < 5; m++) wv[m] = wd[m];
            #pragma unroll
            for (int m = 0; m < 5; m++) {
                fma2(acc[m][0], wv[m], x01.x);
                fma2(acc[m][1], wv[m], x01.y);
                fma2(acc[m][2], wv[m], x23.x);
                fma2(acc[m][3], wv[m], x23.y);
            }
        }
    }

    // ---- stage y t-major in smem (XI2 now dead), coalesced global store ----
    __syncthreads();
    if (gact) {
        #pragma unroll
        for (int m = 0; m < 5; m++) {
            int o = og * 5 + m;
            #pragma unroll
            for (int q = 0; q < 4; q++) {
                int t = 2 * (gtg * 4 + q);
                float lo, hi; unpack2(acc[m][q], lo, hi);
                sm[OFF_YST + t * 52 + o]       = lo;
                sm[OFF_YST + (t + 1) * 52 + o] = hi;
            }
        }
    }
    __syncthreads();
    {
        float* yb = g_y + (size_t)t0h * SROWS + b * COUT;
        for (int i = tid; i < len * COUT; i += THREADS) {
            int t = i / COUT, o = i % COUT;
            yb[(size_t)t * SROWS + o] = sm[OFF_YST + t * 52 + o];
        }
    }
}

// ---- scan: coalesced t-major reads, bit-exact refractory recursion (proven verbatim) ----
#define SC_SMEM ((2*32*256 + 256*33) * 4)    // 99,328 B

__global__ __launch_bounds__(256, 2)
void scan_kernel(float* __restrict__ out)
{
    extern __shared__ float ss[];
    float* sbuf = ss + 2 * 32 * 256;
    const int tid = threadIdx.x;
    const int r0 = blockIdx.x * 256;

    {   // prefetch tile 0
        const float* src = g_y + r0;
        for (int j = tid; j < 32 * 256; j += 256) {
            int t = j >> 8, col = j & 255;
            cpa4(smem_u32(ss + t * 256 + col), src + (size_t)t * SROWS + col);
        }
        cpa_commit();
    }

    float nu1[31];
    #pragma unroll
    for (int d = 1; d <= 31; d++) {
        float td = (float)d;
        nu1[d - 1] = (-20.0f * td) * expf(1.0f - td);
    }
    float rf[32];
    #pragma unroll
    for (int i = 0; i < 32; i++) rf[i] = 0.0f;

    for (int tile = 0; tile < 11; tile++) {
        const int tl = (tile == 10) ? 5 : 32;
        if (tile < 10) {
            const int nt = (tile == 9) ? 5 : 32;
            const float* src = g_y + (size_t)(tile + 1) * 32 * SROWS + r0;
            float* dst = ss + ((tile + 1) & 1) * (32 * 256);
            for (int j = tid; j < nt * 256; j += 256) {
                int t = j >> 8, col = j & 255;
                cpa4(smem_u32(dst + t * 256 + col), src + (size_t)t * SROWS + col);
            }
            cpa_commit();
            asm volatile("cp.async.wait_group 1;");
        } else {
            asm volatile("cp.async.wait_group 0;");
        }
        __syncthreads();

        const float* yb = ss + (tile & 1) * (32 * 256);
        #pragma unroll 8
        for (int t = 0; t < tl; t++) {
            float v = yb[t * 256 + tid] + rf[0];
            float s = (v >= 10.0f) ? 1.0f : 0.0f;
            sbuf[tid * 33 + t] = s;
            #pragma unroll
            for (int i = 0; i < 31; i++) rf[i] = fmaf(s, nu1[i], rf[i + 1]);
            rf[31] = 0.0f;
        }
        __syncthreads();

        const int tbase = tile * 32;
        const int lane = tid & 31;
        for (int base = 0; base < 256; base += 8) {
            int row = base + (tid >> 5);
            if (lane < tl)
                out[(size_t)(r0 + row) * TT + tbase + lane] = sbuf[row * 33 + lane];
        }
        // loop-top __syncthreads orders flush reads before next tile's writes
    }
}

extern "C" void kernel_launch(void* const* d_in, const int* in_sizes, int n_in,
                              void* d_out, int out_size)
{
    const float* x = (const float*)d_in[0];
    const float* w = (const float*)d_in[1];
    if (n_in >= 2 && in_sizes[0] == COUT * CIN) {
        x = (const float*)d_in[1];
        w = (const float*)d_in[0];
    }
    cudaFuncSetAttribute(convgemm_kernel, cudaFuncAttributeMaxDynamicSharedMemorySize,
                         SMEM_FLOATS * (int)sizeof(float));
    cudaFuncSetAttribute(scan_kernel, cudaFuncAttributeMaxDynamicSharedMemorySize,
                         SC_SMEM);
    convgemm_kernel<<<NB * 2, THREADS, SMEM_FLOATS * sizeof(float)>>>(x, w);
    scan_kernel<<<SROWS / 256, 256, SC_SMEM>>>((float*)d_out);
}

// round 16
// speedup vs baseline: 1.4191x; 1.4110x over previous
#include <cuda_runtime.h>
#include <math.h>

#define NB   512
#define CIN  156
#define COUT 50
#define TT   325
#define THREADS 256

#define CCH   26
#define NCH   6
#define NPAIR 13

// conv: 13 pairs x 17 t-groups, tile 10 (proven)
#define CNTG  17
#define CTILE 10
#define CACT  221

// gemm: 5 o-groups (10 o each) x 41 t-groups (2 ulls = 4 t each)
#define GNTG  41
#define GACT  205

#define XROW2F 544                 // floats per interleaved pair row (272 ulls)
#define XI2BUF (NPAIR*XROW2F)      // 7072 floats
#define PSTR   168
#define PSPBUF (CCH*PSTR)          // 4368 floats
#define WDBUF  (CCH*COUT*2)        // 2600 floats (dup ulls)

// smem float offsets (per CTA, 113,120 B -> 2 CTAs/SM)
#define OFF_EPS 0                  // 200
#define OFF_WD  200                // 2 x 2600
#define OFF_PSP 5400               // 2 x 4368
#define OFF_XI2 14136              // 2 x 7072
#define SMEM_FLOATS 28280
#define OFF_YST OFF_XI2            // y staging [168][52] t-major (reuses XI2)

#define SROWS (NB*COUT)            // 25600

typedef unsigned long long ull;

__device__ float g_y[(size_t)TT * SROWS];   // t-major scratch, 33.3 MB

__device__ __forceinline__ ull pack2(float lo, float hi) {
    ull r; asm("mov.b64 %0, {%1, %2};" : "=l"(r) : "f"(lo), "f"(hi)); return r;
}
__device__ __forceinline__ void unpack2(ull v, float &lo, float &hi) {
    asm("mov.b64 {%0, %1}, %2;" : "=f"(lo), "=f"(hi) : "l"(v));
}
__device__ __forceinline__ void fma2(ull &d, ull a, ull b) {
    asm("fma.rn.f32x2 %0, %1, %2, %0;" : "+l"(d) : "l"(a), "l"(b));
}
__device__ __forceinline__ unsigned smem_u32(const void* p) {
    return (unsigned)__cvta_generic_to_shared(p);
}
__device__ __forceinline__ void cpa4(unsigned dst, const float* src) {
    asm volatile("cp.async.ca.shared.global [%0], [%1], 4;" :: "r"(dst), "l"(src));
}
__device__ __forceinline__ void cpa_commit() { asm volatile("cp.async.commit_group;"); }

__global__ __launch_bounds__(THREADS, 2)
void convgemm_kernel(const float* __restrict__ x, const float* __restrict__ w)
{
    extern __shared__ float sm[];
    const int tid = threadIdx.x;
    const int b   = blockIdx.x >> 1;
    const int h   = blockIdx.x & 1;
    const int len = 163 - h;               // 163 / 162
    const int t0h = h * 163;
    const int pstart = h ? 0 : 100;
    const int cnt = 100 + len - pstart;

    // ---- init: eps taps (jnp op sequence), x pads, psp tails ----
    if (tid < 100) {
        float tk = (float)tid / 10.0f;
        float e  = tk * expf(1.0f - tk);
        ((ull*)(sm + OFF_EPS))[tid] = pack2(e, e);
    }
    for (int i = tid; i < NPAIR * 200 * 2; i += THREADS) {       // zero x pads, both bufs
        int buf = i / (NPAIR * 200), rem = i % (NPAIR * 200);
        sm[OFF_XI2 + buf * XI2BUF + (rem / 200) * XROW2F + (rem % 200)] = 0.0f;
    }
    for (int i = tid; i < 2 * CCH * (PSTR - len); i += THREADS) {  // zero psp tails
        int buf = i / (CCH * (PSTR - len)), rem = i % (CCH * (PSTR - len));
        int row = rem / (PSTR - len), off = rem % (PSTR - len);
        sm[OFF_PSP + buf * PSPBUF + row * PSTR + len + off] = 0.0f;
    }

    // ---- prologue: issue x chunk 0, load w chunk 0 into regs ----
    {
        const float* xb = x + ((size_t)b * CIN) * TT + (t0h - 100);
        for (int i = tid; i < CCH * cnt; i += THREADS) {
            int cl = i / cnt, p = pstart + i % cnt;
            cpa4(smem_u32(sm + OFF_XI2 + (cl >> 1) * XROW2F + 2 * p + (cl & 1)),
                 xb + cl * TT + p);
        }
        cpa_commit();
    }
    float wR[6];
    {
        int j = 0;
        for (int i = tid; i < CCH * COUT; i += THREADS, j++) {
            int o = i / CCH, cl = i % CCH;
            wR[j] = w[o * CIN + cl];
        }
    }

    // thread mappings
    const int cpr = tid / CNTG, ctg = tid % CNTG;
    const int ct0 = ctg * CTILE;
    const bool cact = (tid < CACT);
    const ull* e2 = (const ull*)(sm + OFF_EPS);

    const int og = tid / GNTG;                 // 0..4
    const int gtg = tid % GNTG;                // 0..40
    const int gt0fl = gtg * 4;
    const bool gact = (tid < GACT);

    ull acc[10][2];
    #pragma unroll
    for (int m = 0; m < 10; m++) { acc[m][0] = 0ULL; acc[m][1] = 0ULL; }

    // ---- pipelined main loop: ONE barrier per chunk ----
    // body cc: issue x[cc+1] | write Wd[cc] | conv[cc] | GEMM[cc-1]
    for (int cc = 0; cc < NCH; cc++) {
        asm volatile("cp.async.wait_group 0;");
        __syncthreads();
        // barrier[cc]: x[cc] visible; PSP/Wd[cc-1] visible; conv[cc-1] reads done.

        if (cc + 1 < NCH) {
            const float* xb = x + ((size_t)b * CIN + (cc + 1) * CCH) * TT + (t0h - 100);
            float* dstb = sm + OFF_XI2 + ((cc + 1) & 1) * XI2BUF;
            for (int i = tid; i < CCH * cnt; i += THREADS) {
                int cl = i / cnt, p = pstart + i % cnt;
                cpa4(smem_u32(dstb + (cl >> 1) * XROW2F + 2 * p + (cl & 1)),
                     xb + cl * TT + p);
            }
            cpa_commit();
        }

        // Wd[cc&1] from wR (two STS.32, proven form); prefetch w[cc+1] into regs
        {
            float* wdst = sm + OFF_WD + (cc & 1) * WDBUF;
            int j = 0;
            for (int i = tid; i < CCH * COUT; i += THREADS, j++) {
                int o = i / CCH, cl = i % CCH;
                wdst[(cl * COUT + o) * 2]     = wR[j];
                wdst[(cl * COUT + o) * 2 + 1] = wR[j];
            }
            if (cc + 1 < NCH) {
                j = 0;
                for (int i = tid; i < CCH * COUT; i += THREADS, j++) {
                    int o = i / CCH, cl = i % CCH;
                    wR[j] = w[o * CIN + (cc + 1) * CCH + cl];
                }
            }
        }

        // ---- conv[cc]: 100-tap FIR, ascending k, shift-4 window W[14] (R11 verbatim) ----
        if (cact) {
            const float* rowf = sm + OFF_XI2 + (cc & 1) * XI2BUF + cpr * XROW2F;
            float* pspb = sm + OFF_PSP + (cc & 1) * PSPBUF;
            ull acc2[CTILE];
            #pragma unroll
            for (int j = 0; j < CTILE; j++) acc2[j] = 0ULL;

            ull W[14];
            {
                const ulonglong2* p = (const ulonglong2*)(rowf + 2 * (96 + ct0));
                #pragma unroll
                for (int m = 0; m < 7; m++) { ulonglong2 v = p[m]; W[2*m] = v.x; W[2*m+1] = v.y; }
            }
            #pragma unroll
            for (int kk = 0; kk < 100; kk += 4) {
                #pragma unroll
                for (int i = 0; i < 4; i++) {
                    ull ek = e2[kk + i];
                    #pragma unroll
                    for (int j = 0; j < CTILE; j++)
                        fma2(acc2[j], ek, W[j - i + 4]);
                }
                if (kk < 96) {
                    #pragma unroll
                    for (int m = 13; m >= 4; m--) W[m] = W[m - 4];
                    const ulonglong2* p = (const ulonglong2*)(rowf + 2 * (92 + ct0 - kk));
                    ulonglong2 v0 = p[0], v1 = p[1];
                    W[0] = v0.x; W[1] = v0.y; W[2] = v1.x; W[3] = v1.y;
                }
            }
            #pragma unroll
            for (int j = 0; j < CTILE; j++) {
                int t = ct0 + j;
                if (t < len) {
                    float lo, hi; unpack2(acc2[j], lo, hi);
                    pspb[(2 * cpr)     * PSTR + t] = lo;
                    pspb[(2 * cpr + 1) * PSTR + t] = hi;
                }
            }
        }

        // ---- GEMM[cc-1]: lane-contiguous x (one LDS.128/ch), w broadcast ----
        if (cc > 0 && gact) {
            const int g = cc - 1;
            const float* pspb = sm + OFF_PSP + (g & 1) * PSPBUF;
            const ull* wdb = (const ull*)(sm + OFF_WD + (g & 1) * WDBUF);
            #pragma unroll 2
            for (int cl = 0; cl < CCH; cl++) {
                ulonglong2 xv = *(const ulonglong2*)(pspb + cl * PSTR + gt0fl);
                const ull* wd = wdb + cl * COUT + og * 10;
                ull wv[10];
                #pragma unroll
                for (int m = 0; m < 10; m++) wv[m] = wd[m];
                #pragma unroll
                for (int m = 0; m < 10; m++) {
                    fma2(acc[m][0], wv[m], xv.x);
                    fma2(acc[m][1], wv[m], xv.y);
                }
            }
        }
    }

    // ---- drain: GEMM[5] ----
    __syncthreads();
    if (gact) {
        const float* pspb = sm + OFF_PSP + ((NCH - 1) & 1) * PSPBUF;
        const ull* wdb = (const ull*)(sm + OFF_WD + ((NCH - 1) & 1) * WDBUF);
        #pragma unroll 2
        for (int cl = 0; cl < CCH; cl++) {
            ulonglong2 xv = *(const ulonglong2*)(pspb + cl * PSTR + gt0fl);
            const ull* wd = wdb + cl * COUT + og * 10;
            ull wv[10];
            #pragma unroll
            for (int m = 0; m < 10; m++) wv[m] = wd[m];
            #pragma unroll
            for (int m = 0; m < 10; m++) {
                fma2(acc[m][0], wv[m], xv.x);
                fma2(acc[m][1], wv[m], xv.y);
            }
        }
    }

    // ---- stage y t-major in smem (XI2 now dead), coalesced global store ----
    __syncthreads();
    if (gact) {
        #pragma unroll
        for (int m = 0; m < 10; m++) {
            int o = og * 10 + m;
            #pragma unroll
            for (int q = 0; q < 2; q++) {
                int t = gt0fl + 2 * q;
                float lo, hi; unpack2(acc[m][q], lo, hi);
                sm[OFF_YST + t * 52 + o]       = lo;
                sm[OFF_YST + (t + 1) * 52 + o] = hi;
            }
        }
    }
    __syncthreads();
    {
        float* yb = g_y + (size_t)t0h * SROWS + b * COUT;
        for (int i = tid; i < len * COUT; i += THREADS) {
            int t = i / COUT, o = i % COUT;
            yb[(size_t)t * SROWS + o] = sm[OFF_YST + t * 52 + o];
        }
    }
}

// ---- scan: coalesced t-major reads, bit-exact refractory recursion (proven verbatim) ----
#define SC_SMEM ((2*32*256 + 256*33) * 4)    // 99,328 B

__global__ __launch_bounds__(256, 2)
void scan_kernel(float* __restrict__ out)
{
    extern __shared__ float ss[];
    float* sbuf = ss + 2 * 32 * 256;
    const int tid = threadIdx.x;
    const int r0 = blockIdx.x * 256;

    {   // prefetch tile 0
        const float* src = g_y + r0;
        for (int j = tid; j < 32 * 256; j += 256) {
            int t = j >> 8, col = j & 255;
            cpa4(smem_u32(ss + t * 256 + col), src + (size_t)t * SROWS + col);
        }
        cpa_commit();
    }

    float nu1[31];
    #pragma unroll
    for (int d = 1; d <= 31; d++) {
        float td = (float)d;
        nu1[d - 1] = (-20.0f * td) * expf(1.0f - td);
    }
    float rf[32];
    #pragma unroll
    for (int i = 0; i < 32; i++) rf[i] = 0.0f;

    for (int tile = 0; tile < 11; tile++) {
        const int tl = (tile == 10) ? 5 : 32;
        if (tile < 10) {
            const int nt = (tile == 9) ? 5 : 32;
            const float* src = g_y + (size_t)(tile + 1) * 32 * SROWS + r0;
            float* dst = ss + ((tile + 1) & 1) * (32 * 256);
            for (int j = tid; j < nt * 256; j += 256) {
                int t = j >> 8, col = j & 255;
                cpa4(smem_u32(dst + t * 256 + col), src + (size_t)t * SROWS + col);
            }
            cpa_commit();
            asm volatile("cp.async.wait_group 1;");
        } else {
            asm volatile("cp.async.wait_group 0;");
        }
        __syncthreads();

        const float* yb = ss + (tile & 1) * (32 * 256);
        #pragma unroll 8
        for (int t = 0; t < tl; t++) {
            float v = yb[t * 256 + tid] + rf[0];
            float s = (v >= 10.0f) ? 1.0f : 0.0f;
            sbuf[tid * 33 + t] = s;
            #pragma unroll
            for (int i = 0; i < 31; i++) rf[i] = fmaf(s, nu1[i], rf[i + 1]);
            rf[31] = 0.0f;
        }
        __syncthreads();

        const int tbase = tile * 32;
        const int lane = tid & 31;
        for (int base = 0; base < 256; base += 8) {
            int row = base + (tid >> 5);
            if (lane < tl)
                out[(size_t)(r0 + row) * TT + tbase + lane] = sbuf[row * 33 + lane];
        }
        // loop-top __syncthreads orders flush reads before next tile's writes
    }
}

extern "C" void kernel_launch(void* const* d_in, const int* in_sizes, int n_in,
                              void* d_out, int out_size)
{
    const float* x = (const float*)d_in[0];
    const float* w = (const float*)d_in[1];
    if (n_in >= 2 && in_sizes[0] == COUT * CIN) {
        x = (const float*)d_in[1];
        w = (const float*)d_in[0];
    }
    cudaFuncSetAttribute(convgemm_kernel, cudaFuncAttributeMaxDynamicSharedMemorySize,
                         SMEM_FLOATS * (int)sizeof(float));
    cudaFuncSetAttribute(scan_kernel, cudaFuncAttributeMaxDynamicSharedMemorySize,
                         SC_SMEM);
    convgemm_kernel<<<NB * 2, THREADS, SMEM_FLOATS * sizeof(float)>>>(x, w);
    scan_kernel<<<SROWS / 256, 256, SC_SMEM>>>((float*)d_out);
}